// round 12
// baseline (speedup 1.0000x reference)
#include <cuda_runtime.h>
#include <cuda_fp16.h>
#include <cstdint>

#define NB 8
#define NN 2048
#define NF 512

// ---------------- device scratch (allocation-free rule) ----------------
__device__ float g_s[NB * NN];
__device__ __half g_A[(size_t)NB * NN * NN];   // A+I fp16, 64 MB
__device__ __half g_X[(size_t)NB * NN * NF];   // 16 MB
__device__ __half g_W[(size_t)NF * NF];        // W row-major [k][f]
__device__ __half g_y[(size_t)NB * NN * NF];   // y row-major [node][f]

// ---------------- helpers ----------------
__device__ __forceinline__ uint32_t smem_u32(const void* p) {
    uint32_t a;
    asm("{ .reg .u64 t; cvta.to.shared.u64 t, %1; cvt.u32.u64 %0, t; }"
        : "=r"(a) : "l"(p));
    return a;
}
__device__ __forceinline__ uint32_t swzA(uint32_t off) { return off ^ ((off >> 3) & 0x70); }

#define CP16(dst, src) \
    asm volatile("cp.async.cg.shared.global [%0], [%1], 16;" :: "r"(dst), "l"(src))
#define CP_COMMIT() asm volatile("cp.async.commit_group;" ::: "memory")

#define LDSM4(r0, r1, r2, r3, addr) \
    asm volatile("ldmatrix.sync.aligned.m8n8.x4.shared.b16 {%0,%1,%2,%3}, [%4];" \
                 : "=r"(r0), "=r"(r1), "=r"(r2), "=r"(r3) : "r"(addr))
#define LDSM4T(r0, r1, r2, r3, addr) \
    asm volatile("ldmatrix.sync.aligned.m8n8.x4.trans.shared.b16 {%0,%1,%2,%3}, [%4];" \
                 : "=r"(r0), "=r"(r1), "=r"(r2), "=r"(r3) : "r"(addr))

#define MMA16816(c, a, b) \
    asm("mma.sync.aligned.m16n8k16.row.col.f32.f16.f16.f32 " \
        "{%0,%1,%2,%3}, {%4,%5,%6,%7}, {%8,%9}, {%0,%1,%2,%3};" \
        : "+f"((c)[0]), "+f"((c)[1]), "+f"((c)[2]), "+f"((c)[3]) \
        : "r"((a)[0]), "r"((a)[1]), "r"((a)[2]), "r"((a)[3]), \
          "r"((b)[0]), "r"((b)[1]))

// ---------------- conversion kernels ----------------
// A -> (A+I) fp16 + degree scale. 128 thr/row, 16 elems/thread (MLP=4).
__global__ void convA_kernel(const float* __restrict__ A) {
    const int row = blockIdx.x;                    // 0 .. NB*NN-1
    const int node = row & (NN - 1);
    const float* src = A + (size_t)row * NN;
    __half* d = g_A + (size_t)row * NN;
    const int t = threadIdx.x;                     // 128 thr
    const int e0 = t * 16;
    float4 v4[4];
    #pragma unroll
    for (int i = 0; i < 4; i++) v4[i] = *(const float4*)(src + e0 + i * 4);
    float* v = (float*)v4;
    if (node >= e0 && node < e0 + 16) v[node - e0] += 1.0f;   // +I
    alignas(16) __half h[16];
    float sum = 0.f;
    #pragma unroll
    for (int i = 0; i < 16; i++) {
        sum += v[i];
        h[i] = __float2half(v[i]);
    }
    *(uint4*)(d + e0) = *(uint4*)h;
    *(uint4*)(d + e0 + 8) = *(uint4*)(h + 8);
    __shared__ float red[4];
    #pragma unroll
    for (int o = 16; o; o >>= 1) sum += __shfl_down_sync(0xffffffff, sum, o);
    if ((t & 31) == 0) red[t >> 5] = sum;
    __syncthreads();
    if (t == 0) g_s[row] = rsqrtf(red[0] + red[1] + red[2] + red[3]);
}

// X and W -> fp16, merged into one launch
__global__ void convXW_kernel(const float* __restrict__ X,
                              const float* __restrict__ W) {
    const int row = blockIdx.x;
    const float* src;
    __half* d;
    if (row < NB * NN) {
        src = X + (size_t)row * NF;
        d = g_X + (size_t)row * NF;
    } else {
        const int r = row - NB * NN;
        src = W + (size_t)r * NF;
        d = g_W + (size_t)r * NF;
    }
    const int t = threadIdx.x;                     // 64 thr, 8 elems each
    float4 v0 = *(const float4*)(src + t * 8);
    float4 v1 = *(const float4*)(src + t * 8 + 4);
    float v[8] = {v0.x, v0.y, v0.z, v0.w, v1.x, v1.y, v1.z, v1.w};
    alignas(16) __half h[8];
    #pragma unroll
    for (int i = 0; i < 8; i++) h[i] = __float2half(v[i]);
    *(uint4*)(d + t * 8) = *(uint4*)h;
}

// y <- s * y'  (after convA and gemm1 have both finished)
__global__ void scale_y_kernel() {
    const int row = blockIdx.x;                    // b*NN + node
    const float s = g_s[row];
    __half* y = g_y + (size_t)row * NF;
    const int t = threadIdx.x;                     // 64 thr, 8 halfs each
    uint4 v = *(uint4*)(y + t * 8);
    __half2* h2 = (__half2*)&v;
    #pragma unroll
    for (int i = 0; i < 4; i++) {
        float2 f = __half22float2(h2[i]);
        f.x *= s; f.y *= s;
        h2[i] = __float22half2_rn(f);
    }
    *(uint4*)(y + t * 8) = v;
}

// ---------------- HMMA GEMM (single fp16) ----------------
// CTA tile M=128, N=256. 8 warps = 2(m) x 4(n); warp tile 64x64.
template <int KTOT, int NSUB, int NSTAGE, bool IS_XW>
__global__ __launch_bounds__(256, 1)
void gemm_kernel(const float* __restrict__ bias, float* __restrict__ out) {
    constexpr int KCHUNK = NSUB * 64;
    constexpr int NCH = KTOT / KCHUNK;
    constexpr int STAGE_BYTES = NSUB * 49152;
    constexpr int BOFF = NSUB * 16384;
    extern __shared__ __align__(1024) char smem[];
    const uint32_t sb = smem_u32(smem);

    const int tid = threadIdx.x;
    const int wid = tid >> 5;
    const int lane = tid & 31;
    const int wm = wid >> 2;       // 2 m-tiles of 64
    const int wn = wid & 3;        // 4 n-tiles of 64

    const int bb = blockIdx.z;
    const int m0 = blockIdx.y * 128;
    const int n0 = blockIdx.x * 256;

    const __half *pA, *pB;
    size_t lda;
    if (IS_XW) {
        lda = NF;
        pA = g_X + ((size_t)bb * NN + m0) * NF;
        pB = g_W + n0;                          // [k][n], ld = NF
    } else {
        lda = NN;
        pA = g_A + ((size_t)bb * NN + m0) * NN;
        pB = g_y + (size_t)bb * NN * NF + n0;   // y [node][f], ld = NF
    }

    auto load_stage = [&](int s, int chunk) {
        const uint32_t base = sb + (uint32_t)s * STAGE_BYTES;
        const int k0 = chunk * KCHUNK;
        #pragma unroll
        for (int j = 0; j < NSUB; j++) {
            const int kj = k0 + j * 64;
            #pragma unroll
            for (int i = 0; i < 4; i++) {          // A sub: 128 rows x 8 x 16B
                int g = tid + i * 256;
                int r = g >> 3, c = g & 7;
                uint32_t so = swzA((uint32_t)(r * 128 + c * 16));
                CP16(base + j * 16384 + so,
                     (const char*)(pA + (size_t)r * lda + kj) + c * 16);
            }
            #pragma unroll
            for (int i = 0; i < 8; i++) {          // B sub: 64 k-rows x 32 x 16B
                int g = tid + i * 256;
                int k = g >> 5, c = g & 31;
                uint32_t so = (uint32_t)(k * 512 + ((c * 16) ^ ((k & 7) << 4)));
                CP16(base + BOFF + j * 32768 + so,
                     (const char*)(pB + (size_t)(kj + k) * NF) + c * 16);
            }
        }
        CP_COMMIT();
    };

    float c[4][8][4];
    #pragma unroll
    for (int i = 0; i < 4; i++)
        #pragma unroll
        for (int j = 0; j < 8; j++)
            #pragma unroll
            for (int k = 0; k < 4; k++) c[i][j][k] = 0.f;

    const int a_row = wm * 64 + (lane & 15);
    const int a_kb  = (lane >> 4) * 16;
    const int b_krow = lane & 15;
    const uint32_t b_swz = (uint32_t)(b_krow & 7) << 4;
    const int b_nbyte = wn * 128 + (lane >> 4) * 16;

    #pragma unroll
    for (int s = 0; s < NSTAGE - 1 && s < NCH; s++) load_stage(s, s);

    #pragma unroll 1
    for (int i = 0; i < NCH; i++) {
        if (i + NSTAGE - 1 < NCH)
            asm volatile("cp.async.wait_group %0;" :: "n"(NSTAGE - 2) : "memory");
        else
            asm volatile("cp.async.wait_group 0;" ::: "memory");
        __syncthreads();
        if (i + NSTAGE - 1 < NCH)
            load_stage((i + NSTAGE - 1) % NSTAGE, i + NSTAGE - 1);

        const uint32_t base = sb + (uint32_t)(i % NSTAGE) * STAGE_BYTES;
        #pragma unroll
        for (int ks_ = 0; ks_ < NSUB * 4; ks_++) {
            const int sub = ks_ >> 2;
            const int ks = ks_ & 3;
            const uint32_t abase = base + sub * 16384;
            const uint32_t bbase = base + BOFF + sub * 32768;
            uint32_t ah[4][4];
            #pragma unroll
            for (int mf = 0; mf < 4; mf++) {
                uint32_t off = swzA((uint32_t)((a_row + mf * 16) * 128 + ks * 32 + a_kb));
                LDSM4(ah[mf][0], ah[mf][1], ah[mf][2], ah[mf][3], abase + off);
            }
            #pragma unroll
            for (int nb = 0; nb < 4; nb++) {
                uint32_t bh[2][2];
                uint32_t addr = bbase + (uint32_t)((ks * 16 + b_krow) * 512) +
                                ((uint32_t)(b_nbyte + nb * 32) ^ b_swz);
                LDSM4T(bh[0][0], bh[0][1], bh[1][0], bh[1][1], addr);
                #pragma unroll
                for (int mf = 0; mf < 4; mf++) MMA16816(c[mf][2*nb],   ah[mf], bh[0]);
                #pragma unroll
                for (int mf = 0; mf < 4; mf++) MMA16816(c[mf][2*nb+1], ah[mf], bh[1]);
            }
        }
    }

    // ---------------- epilogue ----------------
    const int g4 = lane >> 2;
    const int tq = lane & 3;
    #pragma unroll
    for (int mf = 0; mf < 4; mf++) {
        #pragma unroll
        for (int half = 0; half < 2; half++) {
            const int m = m0 + wm * 64 + mf * 16 + g4 + half * 8;
            if (IS_XW) {
                // unscaled: convA may still be running (g_s not ready)
                __half* yr = g_y + ((size_t)bb * NN + m) * NF;
                #pragma unroll
                for (int nf = 0; nf < 8; nf++) {
                    const int f = n0 + wn * 64 + nf * 8 + tq * 2;
                    float2 bs = *(const float2*)(bias + f);
                    __half2 hv;
                    hv.x = __float2half(c[mf][nf][half * 2 + 0] + bs.x);
                    hv.y = __float2half(c[mf][nf][half * 2 + 1] + bs.y);
                    *(__half2*)(yr + f) = hv;
                }
            } else {
                const float s = g_s[bb * NN + m];
                float* orow = out + ((size_t)bb * NN + m) * NF;
                #pragma unroll
                for (int nf = 0; nf < 8; nf++) {
                    const int f = n0 + wn * 64 + nf * 8 + tq * 2;
                    float2 o;
                    o.x = s * c[mf][nf][half * 2 + 0];
                    o.y = s * c[mf][nf][half * 2 + 1];
                    *(float2*)(orow + f) = o;
                }
            }
        }
    }
}

// ---------------- launch ----------------
namespace {
struct ForkResources {
    cudaStream_t s1, s2;
    cudaEvent_t evFork, evA, evDone;
    ForkResources() {
        cudaStreamCreateWithFlags(&s1, cudaStreamNonBlocking);
        cudaStreamCreateWithFlags(&s2, cudaStreamNonBlocking);
        cudaEventCreateWithFlags(&evFork, cudaEventDisableTiming);
        cudaEventCreateWithFlags(&evA, cudaEventDisableTiming);
        cudaEventCreateWithFlags(&evDone, cudaEventDisableTiming);
    }
};
}  // namespace

extern "C" void kernel_launch(void* const* d_in, const int* in_sizes, int n_in,
                              void* d_out, int out_size) {
    const float* X    = (const float*)d_in[0];   // [8,2048,512]
    const float* A    = (const float*)d_in[1];   // [8,2048,2048]
    const float* W    = (const float*)d_in[2];   // [512,512]
    const float* bias = (const float*)d_in[3];   // [512]
    float* out = (float*)d_out;                  // [8,2048,512]

    static ForkResources fr;   // created on first (un-captured) correctness call

    constexpr int SMEM1 = 3 * 49152;             // gemm1: k64 chunks, 3-stage
    constexpr int SMEM2 = 2 * 2 * 49152;         // gemm2: k128 chunks, 2-stage
    cudaFuncSetAttribute((const void*)gemm_kernel<NF, 1, 3, true>,
                         cudaFuncAttributeMaxDynamicSharedMemorySize, SMEM1);
    cudaFuncSetAttribute((const void*)gemm_kernel<NN, 2, 2, false>,
                         cudaFuncAttributeMaxDynamicSharedMemorySize, SMEM2);

    dim3 grid(NF / 256, NN / 128, NB);           // (2, 16, 8) = 256 CTAs

    // fork: BOTH branches on explicit non-blocking streams (legacy stream
    // issues nothing between fork and join, so no implicit serialization).
    cudaEventRecord(fr.evFork, 0);
    cudaStreamWaitEvent(fr.s1, fr.evFork, 0);
    cudaStreamWaitEvent(fr.s2, fr.evFork, 0);

    // s2: A+I -> fp16 + degree (DRAM-bound)
    convA_kernel<<<NB * NN, 128, 0, fr.s2>>>(A);
    cudaEventRecord(fr.evA, fr.s2);

    // s1: X/W conversion + gemm1 (y' = XW + b, unscaled, compute-bound)
    convXW_kernel<<<NB * NN + NF, 64, 0, fr.s1>>>(X, W);
    gemm_kernel<NF, 1, 3, true><<<grid, 256, SMEM1, fr.s1>>>(bias, out);

    // join on s1, then y = s*y' and the aggregation GEMM
    cudaStreamWaitEvent(fr.s1, fr.evA, 0);
    scale_y_kernel<<<NB * NN, 64, 0, fr.s1>>>();
    gemm_kernel<NN, 2, 2, false><<<grid, 256, SMEM2, fr.s1>>>(bias, out);
    cudaEventRecord(fr.evDone, fr.s1);

    // hand control back to the caller's (legacy) stream
    cudaStreamWaitEvent(0, fr.evDone, 0);
}

// round 13
// speedup vs baseline: 1.0633x; 1.0633x over previous
#include <cuda_runtime.h>
#include <cuda_fp16.h>
#include <cstdint>

#define NB 8
#define NN 2048
#define NF 512

// ---------------- device scratch (allocation-free rule) ----------------
__device__ float g_s[NB * NN];
__device__ __half g_A[(size_t)NB * NN * NN];   // A+I fp16, 64 MB
__device__ __half g_X[(size_t)NB * NN * NF];   // 16 MB
__device__ __half g_W[(size_t)NF * NF];        // W row-major [k][f]
__device__ __half g_y[(size_t)NB * NN * NF];   // y row-major [node][f]

// ---------------- helpers ----------------
__device__ __forceinline__ uint32_t smem_u32(const void* p) {
    uint32_t a;
    asm("{ .reg .u64 t; cvta.to.shared.u64 t, %1; cvt.u32.u64 %0, t; }"
        : "=r"(a) : "l"(p));
    return a;
}
__device__ __forceinline__ uint32_t swzA(uint32_t off) { return off ^ ((off >> 3) & 0x70); }

#define CP16(dst, src) \
    asm volatile("cp.async.cg.shared.global [%0], [%1], 16;" :: "r"(dst), "l"(src))
#define CP_COMMIT() asm volatile("cp.async.commit_group;" ::: "memory")

#define LDSM4(r0, r1, r2, r3, addr) \
    asm volatile("ldmatrix.sync.aligned.m8n8.x4.shared.b16 {%0,%1,%2,%3}, [%4];" \
                 : "=r"(r0), "=r"(r1), "=r"(r2), "=r"(r3) : "r"(addr))
#define LDSM4T(r0, r1, r2, r3, addr) \
    asm volatile("ldmatrix.sync.aligned.m8n8.x4.trans.shared.b16 {%0,%1,%2,%3}, [%4];" \
                 : "=r"(r0), "=r"(r1), "=r"(r2), "=r"(r3) : "r"(addr))

#define MMA16816(c, a, b) \
    asm("mma.sync.aligned.m16n8k16.row.col.f32.f16.f16.f32 " \
        "{%0,%1,%2,%3}, {%4,%5,%6,%7}, {%8,%9}, {%0,%1,%2,%3};" \
        : "+f"((c)[0]), "+f"((c)[1]), "+f"((c)[2]), "+f"((c)[3]) \
        : "r"((a)[0]), "r"((a)[1]), "r"((a)[2]), "r"((a)[3]), \
          "r"((b)[0]), "r"((b)[1]))

// ---------------- merged conversion kernel ----------------
// blocks [0, NB*NN)              : A row -> (A+I) fp16 + degree scale
// blocks [NB*NN, 2*NB*NN)        : X row -> fp16
// blocks [2*NB*NN, 2*NB*NN+NF)   : W row -> fp16
__global__ void conv_all_kernel(const float* __restrict__ A,
                                const float* __restrict__ X,
                                const float* __restrict__ W) {
    const int bid = blockIdx.x;
    const int t = threadIdx.x;                     // 128 thr
    if (bid < NB * NN) {
        const int row = bid;
        const int node = row & (NN - 1);
        const float* src = A + (size_t)row * NN;
        __half* d = g_A + (size_t)row * NN;
        const int e0 = t * 16;
        float4 v4[4];
        #pragma unroll
        for (int i = 0; i < 4; i++) v4[i] = *(const float4*)(src + e0 + i * 4);
        float* v = (float*)v4;
        if (node >= e0 && node < e0 + 16) v[node - e0] += 1.0f;   // +I
        alignas(16) __half h[16];
        float sum = 0.f;
        #pragma unroll
        for (int i = 0; i < 16; i++) {
            sum += v[i];
            h[i] = __float2half(v[i]);
        }
        *(uint4*)(d + e0) = *(uint4*)h;
        *(uint4*)(d + e0 + 8) = *(uint4*)(h + 8);
        __shared__ float red[4];
        #pragma unroll
        for (int o = 16; o; o >>= 1) sum += __shfl_down_sync(0xffffffff, sum, o);
        if ((t & 31) == 0) red[t >> 5] = sum;
        __syncthreads();
        if (t == 0) g_s[row] = rsqrtf(red[0] + red[1] + red[2] + red[3]);
    } else {
        const float* src;
        __half* d;
        if (bid < 2 * NB * NN) {
            const int row = bid - NB * NN;
            src = X + (size_t)row * NF;
            d = g_X + (size_t)row * NF;
        } else {
            const int row = bid - 2 * NB * NN;
            src = W + (size_t)row * NF;
            d = g_W + (size_t)row * NF;
        }
        float4 v = *(const float4*)(src + t * 4);  // 128 thr x 4 elems = 512
        __half2 h0 = __floats2half2_rn(v.x, v.y);
        __half2 h1 = __floats2half2_rn(v.z, v.w);
        uint2 pk;
        pk.x = *(uint32_t*)&h0;
        pk.y = *(uint32_t*)&h1;
        *(uint2*)(d + t * 4) = pk;
    }
}

// ---------------- gemm1: y = s*(X@W + b), CTA tile 64x128, 4 warps ----------------
// warp tile 32x64 (2m x 2n). A [m][k] K-major 128B pitch SW128; B [k][n]
// 256B pitch XOR swizzle, trans-LDSM. 3-stage cp.async, 2 CTAs/SM.
#define G1_ABYTES 8192
#define G1_STAGE 24576
#define G1_SMEM (3 * G1_STAGE)

__global__ __launch_bounds__(128, 2)
void gemm1_kernel(const float* __restrict__ bias) {
    constexpr int NCH = NF / 64;                   // 8
    extern __shared__ __align__(1024) char smem[];
    const uint32_t sb = smem_u32(smem);

    const int tid = threadIdx.x;
    const int wid = tid >> 5;
    const int lane = tid & 31;
    const int wm = wid >> 1;       // 2 m-tiles of 32
    const int wn = wid & 1;        // 2 n-tiles of 64

    const int bb = blockIdx.z;
    const int m0 = blockIdx.y * 64;
    const int n0 = blockIdx.x * 128;

    const __half* pA = g_X + ((size_t)bb * NN + m0) * NF;
    const __half* pB = g_W + n0;

    auto load_stage = [&](int s, int chunk) {
        const uint32_t base = sb + (uint32_t)s * G1_STAGE;
        const int k0 = chunk * 64;
        #pragma unroll
        for (int i = 0; i < 4; i++) {              // A: 64 rows x 8 x 16B
            int g = tid + i * 128;
            int r = g >> 3, c = g & 7;
            uint32_t so = swzA((uint32_t)(r * 128 + c * 16));
            CP16(base + so, (const char*)(pA + (size_t)r * NF + k0) + c * 16);
        }
        #pragma unroll
        for (int i = 0; i < 8; i++) {              // B: 64 k-rows x 16 x 16B
            int g = tid + i * 128;
            int k = g >> 4, c = g & 15;
            uint32_t so = (uint32_t)(k * 256 + ((c * 16) ^ ((k & 7) << 4)));
            CP16(base + G1_ABYTES + so, (const char*)(pB + (size_t)(k0 + k) * NF) + c * 16);
        }
        CP_COMMIT();
    };

    float c[2][8][4];
    #pragma unroll
    for (int i = 0; i < 2; i++)
        #pragma unroll
        for (int j = 0; j < 8; j++)
            #pragma unroll
            for (int k = 0; k < 4; k++) c[i][j][k] = 0.f;

    const int a_row = wm * 32 + (lane & 15);
    const int a_kb  = (lane >> 4) * 16;
    const int b_krow = lane & 15;
    const uint32_t b_swz = (uint32_t)(b_krow & 7) << 4;
    const int b_nbyte = wn * 128 + (lane >> 4) * 16;

    load_stage(0, 0);
    load_stage(1, 1);

    #pragma unroll 1
    for (int i = 0; i < NCH; i++) {
        if (i + 2 < NCH)
            asm volatile("cp.async.wait_group 1;" ::: "memory");
        else
            asm volatile("cp.async.wait_group 0;" ::: "memory");
        __syncthreads();
        if (i + 2 < NCH) load_stage((i + 2) % 3, i + 2);

        const uint32_t base = sb + (uint32_t)(i % 3) * G1_STAGE;
        #pragma unroll
        for (int ks = 0; ks < 4; ks++) {
            uint32_t ah[2][4];
            #pragma unroll
            for (int mf = 0; mf < 2; mf++) {
                uint32_t off = swzA((uint32_t)((a_row + mf * 16) * 128 + ks * 32 + a_kb));
                LDSM4(ah[mf][0], ah[mf][1], ah[mf][2], ah[mf][3], base + off);
            }
            #pragma unroll
            for (int nb = 0; nb < 4; nb++) {
                uint32_t bh[2][2];
                uint32_t addr = base + G1_ABYTES + (uint32_t)((ks * 16 + b_krow) * 256) +
                                ((uint32_t)(b_nbyte + nb * 32) ^ b_swz);
                LDSM4T(bh[0][0], bh[0][1], bh[1][0], bh[1][1], addr);
                #pragma unroll
                for (int mf = 0; mf < 2; mf++) {
                    MMA16816(c[mf][2*nb],   ah[mf], bh[0]);
                    MMA16816(c[mf][2*nb+1], ah[mf], bh[1]);
                }
            }
        }
    }

    const int g4 = lane >> 2;
    const int tq = lane & 3;
    #pragma unroll
    for (int mf = 0; mf < 2; mf++) {
        #pragma unroll
        for (int half = 0; half < 2; half++) {
            const int m = m0 + wm * 32 + mf * 16 + g4 + half * 8;
            const float s = g_s[bb * NN + m];
            __half* yr = g_y + ((size_t)bb * NN + m) * NF;
            #pragma unroll
            for (int nf = 0; nf < 8; nf++) {
                const int f = n0 + wn * 64 + nf * 8 + tq * 2;
                float2 bs = *(const float2*)(bias + f);
                __half2 hv;
                hv.x = __float2half(s * (c[mf][nf][half * 2 + 0] + bs.x));
                hv.y = __float2half(s * (c[mf][nf][half * 2 + 1] + bs.y));
                *(__half2*)(yr + f) = hv;
            }
        }
    }
}

// ---------------- gemm2: out = s*(Ahat @ y), CTA 128x256, k128 chunks ----------------
#define G2_STAGE (2 * 49152)
#define G2_BOFF  (2 * 16384)
#define G2_SMEM  (2 * G2_STAGE)

__global__ __launch_bounds__(256, 1)
void gemm2_kernel(float* __restrict__ out) {
    constexpr int NCH = NN / 128;                  // 16
    extern __shared__ __align__(1024) char smem[];
    const uint32_t sb = smem_u32(smem);

    const int tid = threadIdx.x;
    const int wid = tid >> 5;
    const int lane = tid & 31;
    const int wm = wid >> 2;       // 2 m-tiles of 64
    const int wn = wid & 3;        // 4 n-tiles of 64

    const int bb = blockIdx.z;
    const int m0 = blockIdx.y * 128;
    const int n0 = blockIdx.x * 256;

    const __half* pA = g_A + ((size_t)bb * NN + m0) * NN;
    const __half* pB = g_y + (size_t)bb * NN * NF + n0;

    auto load_stage = [&](int s, int chunk) {
        const uint32_t base = sb + (uint32_t)s * G2_STAGE;
        const int k0 = chunk * 128;
        #pragma unroll
        for (int j = 0; j < 2; j++) {
            const int kj = k0 + j * 64;
            #pragma unroll
            for (int i = 0; i < 4; i++) {          // A sub: 128 rows x 8 x 16B
                int g = tid + i * 256;
                int r = g >> 3, c = g & 7;
                uint32_t so = swzA((uint32_t)(r * 128 + c * 16));
                CP16(base + j * 16384 + so,
                     (const char*)(pA + (size_t)r * NN + kj) + c * 16);
            }
            #pragma unroll
            for (int i = 0; i < 8; i++) {          // B sub: 64 k-rows x 32 x 16B
                int g = tid + i * 256;
                int k = g >> 5, c = g & 31;
                uint32_t so = (uint32_t)(k * 512 + ((c * 16) ^ ((k & 7) << 4)));
                CP16(base + G2_BOFF + j * 32768 + so,
                     (const char*)(pB + (size_t)(kj + k) * NF) + c * 16);
            }
        }
        CP_COMMIT();
    };

    float c[4][8][4];
    #pragma unroll
    for (int i = 0; i < 4; i++)
        #pragma unroll
        for (int j = 0; j < 8; j++)
            #pragma unroll
            for (int k = 0; k < 4; k++) c[i][j][k] = 0.f;

    const int a_row = wm * 64 + (lane & 15);
    const int a_kb  = (lane >> 4) * 16;
    const int b_krow = lane & 15;
    const uint32_t b_swz = (uint32_t)(b_krow & 7) << 4;
    const int b_nbyte = wn * 128 + (lane >> 4) * 16;

    load_stage(0, 0);

    #pragma unroll 1
    for (int i = 0; i < NCH; i++) {
        asm volatile("cp.async.wait_group 0;" ::: "memory");
        __syncthreads();
        if (i + 1 < NCH) load_stage((i + 1) & 1, i + 1);

        const uint32_t base = sb + (uint32_t)(i & 1) * G2_STAGE;
        #pragma unroll
        for (int ks_ = 0; ks_ < 8; ks_++) {
            const int sub = ks_ >> 2;
            const int ks = ks_ & 3;
            const uint32_t abase = base + sub * 16384;
            const uint32_t bbase = base + G2_BOFF + sub * 32768;
            uint32_t ah[4][4];
            #pragma unroll
            for (int mf = 0; mf < 4; mf++) {
                uint32_t off = swzA((uint32_t)((a_row + mf * 16) * 128 + ks * 32 + a_kb));
                LDSM4(ah[mf][0], ah[mf][1], ah[mf][2], ah[mf][3], abase + off);
            }
            #pragma unroll
            for (int nb = 0; nb < 4; nb++) {
                uint32_t bh[2][2];
                uint32_t addr = bbase + (uint32_t)((ks * 16 + b_krow) * 512) +
                                ((uint32_t)(b_nbyte + nb * 32) ^ b_swz);
                LDSM4T(bh[0][0], bh[0][1], bh[1][0], bh[1][1], addr);
                #pragma unroll
                for (int mf = 0; mf < 4; mf++) MMA16816(c[mf][2*nb],   ah[mf], bh[0]);
                #pragma unroll
                for (int mf = 0; mf < 4; mf++) MMA16816(c[mf][2*nb+1], ah[mf], bh[1]);
            }
        }
    }

    const int g4 = lane >> 2;
    const int tq = lane & 3;
    #pragma unroll
    for (int mf = 0; mf < 4; mf++) {
        #pragma unroll
        for (int half = 0; half < 2; half++) {
            const int m = m0 + wm * 64 + mf * 16 + g4 + half * 8;
            const float s = g_s[bb * NN + m];
            float* orow = out + ((size_t)bb * NN + m) * NF;
            #pragma unroll
            for (int nf = 0; nf < 8; nf++) {
                const int f = n0 + wn * 64 + nf * 8 + tq * 2;
                float2 o;
                o.x = s * c[mf][nf][half * 2 + 0];
                o.y = s * c[mf][nf][half * 2 + 1];
                *(float2*)(orow + f) = o;
            }
        }
    }
}

// ---------------- launch ----------------
extern "C" void kernel_launch(void* const* d_in, const int* in_sizes, int n_in,
                              void* d_out, int out_size) {
    const float* X    = (const float*)d_in[0];   // [8,2048,512]
    const float* A    = (const float*)d_in[1];   // [8,2048,2048]
    const float* W    = (const float*)d_in[2];   // [512,512]
    const float* bias = (const float*)d_in[3];   // [512]
    float* out = (float*)d_out;                  // [8,2048,512]

    cudaFuncSetAttribute(gemm1_kernel,
                         cudaFuncAttributeMaxDynamicSharedMemorySize, G1_SMEM);
    cudaFuncSetAttribute(gemm2_kernel,
                         cudaFuncAttributeMaxDynamicSharedMemorySize, G2_SMEM);

    // one merged conversion pass: A (+degree), X, W
    conv_all_kernel<<<2 * NB * NN + NF, 128>>>(A, X, W);

    // y = s*(XW+b): 64x128 tiles, 1024 CTAs, 2 CTAs/SM
    dim3 grid1(NF / 128, NN / 64, NB);
    gemm1_kernel<<<grid1, 128, G1_SMEM>>>(bias);

    // out = s*(Ahat@y): 128x256 tiles
    dim3 grid2(NF / 256, NN / 128, NB);
    gemm2_kernel<<<grid2, 256, G2_SMEM>>>(out);
}